// round 9
// baseline (speedup 1.0000x reference)
#include <cuda_runtime.h>
#include <cstdint>

#define CC   128
#define KK   32
#define HH   8
#define DHH  16
#define BB   4
#define GG   128
#define MAXN 100352

// ---------------- device scratch (static, allowed) ----------------
__device__ int   g_grid[BB*GG*GG*GG];      // 32 MB voxel hash
__device__ float g_x  [MAXN*CC];           // conv out -> BN/ReLU (in place)
__device__ float g_q  [MAXN*CC];
__device__ float g_o  [MAXN*CC];
__device__ float g_ao [MAXN*CC];
__device__ float g_sum[CC];
__device__ float g_sumsq[CC];
__device__ float g_bkmax[BB*KK];
__device__ float g_bksum[BB*KK];
__device__ float g_ctx[BB*KK*CC];
__device__ float g_khv[2*BB*KK*CC];        // kh then vh, [bk][c]
__device__ float g_wsum[CC*CC];            // bottleneck_w[:, :C] + [:, C:]

// ---------------- init: grid=-1, zero accumulators, build Wsum ----------------
__global__ void k_init_r9(const float* __restrict__ bw) {
    int i = blockIdx.x * blockDim.x + threadIdx.x;
    const int tot = BB*GG*GG*GG;
    for (int idx = i; idx < tot; idx += gridDim.x * blockDim.x) g_grid[idx] = -1;
    if (i < BB*KK*CC) g_ctx[i] = 0.f;
    if (i < CC*CC) {
        int c = i >> 7, j = i & 127;
        g_wsum[i] = bw[c*2*CC + j] + bw[c*2*CC + CC + j];
    }
    if (i < CC) { g_sum[i] = 0.f; g_sumsq[i] = 0.f; }
}

__global__ void k_scatter_r9(const int* __restrict__ coords, int N) {
    int i = blockIdx.x * blockDim.x + threadIdx.x;
    if (i >= N) return;
    int b = coords[4*i], x = coords[4*i+1], y = coords[4*i+2], z = coords[4*i+3];
    g_grid[((b*GG + x)*GG + y)*GG + z] = i;
}

// ---------------- submanifold 3x3x3 conv: 64 pts x 128 out per CTA ----------------
__global__ void __launch_bounds__(256) k_conv_r9(const float* __restrict__ feats,
                                                 const float* __restrict__ Wc,
                                                 const int*   __restrict__ coords,
                                                 int N) {
    __shared__ int   nbr[27][64];
    __shared__ float As[16][64];
    __shared__ float Ws[16][CC];
    const int t  = threadIdx.x;
    const int n0 = blockIdx.x * 64;

    for (int e = t; e < 27*64; e += 256) {
        int k = e / 64, m = e % 64;
        int n = n0 + m, j = -1;
        if (n < N) {
            int b = coords[4*n];
            int x = coords[4*n+1] + k/9 - 1;
            int y = coords[4*n+2] + (k/3)%3 - 1;
            int z = coords[4*n+3] + k%3 - 1;
            if ((unsigned)x < GG && (unsigned)y < GG && (unsigned)z < GG)
                j = g_grid[((b*GG + x)*GG + y)*GG + z];
        }
        nbr[k][m] = j;
    }
    __syncthreads();

    float acc[4][8];
    #pragma unroll
    for (int q = 0; q < 4; q++)
        #pragma unroll
        for (int r = 0; r < 8; r++) acc[q][r] = 0.f;

    const int mi  = t & 15, ci = t >> 4;      // compute mapping
    const int lm  = t >> 2, ljj = (t & 3) * 4; // A-load mapping
    const int lj  = t >> 4, lc  = (t & 15) * 8; // W-load mapping

    for (int k = 0; k < 27; k++) {
        const float* wb = Wc + k * CC * CC;
        const int idxm = nbr[k][lm];
        for (int js = 0; js < 8; js++) {
            const int j0 = js * 16;
            float4 v = make_float4(0.f, 0.f, 0.f, 0.f);
            if (idxm >= 0) v = *(const float4*)(feats + (size_t)idxm*CC + j0 + ljj);
            As[ljj+0][lm] = v.x; As[ljj+1][lm] = v.y;
            As[ljj+2][lm] = v.z; As[ljj+3][lm] = v.w;
            float4 w0 = *(const float4*)(wb + (j0 + lj)*CC + lc);
            float4 w1 = *(const float4*)(wb + (j0 + lj)*CC + lc + 4);
            *(float4*)&Ws[lj][lc]   = w0;
            *(float4*)&Ws[lj][lc+4] = w1;
            __syncthreads();
            #pragma unroll
            for (int jp = 0; jp < 16; jp++) {
                float4 a  = *(const float4*)&As[jp][mi*4];
                float4 b0 = *(const float4*)&Ws[jp][ci*8];
                float4 b1 = *(const float4*)&Ws[jp][ci*8 + 4];
                float av[4] = {a.x, a.y, a.z, a.w};
                float wv[8] = {b0.x, b0.y, b0.z, b0.w, b1.x, b1.y, b1.z, b1.w};
                #pragma unroll
                for (int q = 0; q < 4; q++)
                    #pragma unroll
                    for (int r = 0; r < 8; r++) acc[q][r] += av[q] * wv[r];
            }
            __syncthreads();
        }
    }
    #pragma unroll
    for (int q = 0; q < 4; q++) {
        int n = n0 + mi*4 + q;
        if (n < N) {
            float4 o0 = make_float4(acc[q][0], acc[q][1], acc[q][2], acc[q][3]);
            float4 o1 = make_float4(acc[q][4], acc[q][5], acc[q][6], acc[q][7]);
            *(float4*)(g_x + (size_t)n*CC + ci*8)     = o0;
            *(float4*)(g_x + (size_t)n*CC + ci*8 + 4) = o1;
        }
    }
}

// ---------------- BN stats + apply ----------------
__global__ void k_bnstats_r9(int N) {
    const int c  = threadIdx.x;        // 128 threads
    const int n0 = blockIdx.x * 256;
    float s = 0.f, s2 = 0.f;
    for (int p = 0; p < 256; p++) {
        int n = n0 + p;
        if (n >= N) break;
        float v = g_x[(size_t)n*CC + c];
        s += v; s2 += v * v;
    }
    atomicAdd(&g_sum[c], s);
    atomicAdd(&g_sumsq[c], s2);
}

__global__ void k_bnapply_r9(const float* __restrict__ gamma,
                             const float* __restrict__ beta, int N) {
    __shared__ float scl[CC], sft[CC];
    int t = threadIdx.x;
    if (t < CC) {
        float inv = 1.f / (float)N;
        float mu  = g_sum[t] * inv;
        float var = g_sumsq[t] * inv - mu * mu;
        float a   = gamma[t] * rsqrtf(var + 1e-5f);
        scl[t] = a; sft[t] = beta[t] - mu * a;
    }
    __syncthreads();
    const int tot = N * CC;
    for (int i = blockIdx.x * blockDim.x + t; i < tot; i += gridDim.x * blockDim.x) {
        float v = g_x[i] * scl[i & 127] + sft[i & 127];
        g_x[i] = v > 0.f ? v : 0.f;
    }
}

// ---------------- per-(b,k) softmax-over-n stats ----------------
__global__ void k_bk_r9(const float* __restrict__ probs, const int* __restrict__ coords, int N) {
    const int b = blockIdx.x >> 5, k = blockIdx.x & 31;
    __shared__ float red[256];
    const int t = threadIdx.x;
    float lm = -3.4e38f;
    for (int n = t; n < N; n += 256)
        if (coords[4*n] == b) lm = fmaxf(lm, probs[n*KK + k]);
    red[t] = lm; __syncthreads();
    for (int s = 128; s > 0; s >>= 1) { if (t < s) red[t] = fmaxf(red[t], red[t+s]); __syncthreads(); }
    float m = red[0]; __syncthreads();
    float ls = 0.f;
    for (int n = t; n < N; n += 256)
        if (coords[4*n] == b) ls += __expf(probs[n*KK + k] - m);
    red[t] = ls; __syncthreads();
    for (int s = 128; s > 0; s >>= 1) { if (t < s) red[t] += red[t+s]; __syncthreads(); }
    if (t == 0) { g_bkmax[blockIdx.x] = m; g_bksum[blockIdx.x] = red[0]; }
}

// ---------------- ctx[b,k,c] = sum_n w[b,n,k] * x[n,c] ----------------
__global__ void __launch_bounds__(256) k_ctx_r9(const float* __restrict__ probs,
                                                const int* __restrict__ coords, int N) {
    const int b = blockIdx.y;
    const int base0 = blockIdx.x * 512;
    __shared__ float sm[KK], sinv[KK];
    __shared__ float ws[8][KK];
    __shared__ float xs[8][CC];
    const int t = threadIdx.x;
    if (t < KK) { sm[t] = g_bkmax[b*KK + t]; sinv[t] = 1.f / g_bksum[b*KK + t]; }
    float acc[16];
    #pragma unroll
    for (int i = 0; i < 16; i++) acc[i] = 0.f;
    const int k = t >> 3, cg = t & 7;
    bool did = false;
    __syncthreads();
    for (int g = 0; g < 64; g++) {
        int nb = base0 + g * 8;
        if (nb >= N) break;
        int nchk = nb + (t & 7);
        int match = (nchk < N) && (coords[4*nchk] == b);
        if (!__syncthreads_or(match)) continue;
        did = true;
        {   // weights tile
            int p = t >> 5, k2 = t & 31, nn = nb + p;
            int mt = (nn < N) && (coords[4*nn] == b);
            ws[p][k2] = mt ? __expf(probs[nn*KK + k2] - sm[k2]) * sinv[k2] : 0.f;
        }
        {   // feature tile
            int p = t >> 5, c4 = (t & 31) * 4, nn = nb + p;
            float4 v = make_float4(0.f, 0.f, 0.f, 0.f);
            if (nn < N) v = *(const float4*)(g_x + (size_t)nn*CC + c4);
            *(float4*)&xs[p][c4] = v;
        }
        __syncthreads();
        #pragma unroll
        for (int p = 0; p < 8; p++) {
            float w = ws[p][k];
            #pragma unroll
            for (int i = 0; i < 16; i++) acc[i] += w * xs[p][cg + 8*i];
        }
        __syncthreads();
    }
    if (did) {
        #pragma unroll
        for (int i = 0; i < 16; i++)
            atomicAdd(&g_ctx[(b*KK + k)*CC + cg + 8*i], acc[i]);
    }
}

// ---------------- kh/vh = ctx @ Wk.T/Wv.T + bias ----------------
__global__ void k_khv_r9(const float* __restrict__ ipw, const float* __restrict__ ipb) {
    __shared__ float row[CC];
    const int bk = blockIdx.x, t = threadIdx.x;
    if (t < CC) row[t] = g_ctx[bk*CC + t];
    __syncthreads();
    const int c = t & 127, which = t >> 7;            // 0 = kh, 1 = vh
    const float* wr = ipw + (size_t)(CC + which*CC + c) * CC;
    float s = ipb[CC + which*CC + c];
    #pragma unroll 8
    for (int j = 0; j < CC; j++) s += row[j] * wr[j];
    g_khv[which*BB*KK*CC + bk*CC + c] = s;
}

// ---------------- generic 64x128 SGEMM: out = (A @ W.T + bias) * scale ----------------
template<bool HASB>
__global__ void __launch_bounds__(256) k_gemm_r9(const float* __restrict__ A,
                                                 const float* __restrict__ W,
                                                 const float* __restrict__ bias,
                                                 float* __restrict__ out,
                                                 int N, float scale) {
    __shared__ float As[16][64];
    __shared__ float Ws[16][CC];
    const int t  = threadIdx.x;
    const int n0 = blockIdx.x * 64;
    float acc[4][8];
    #pragma unroll
    for (int q = 0; q < 4; q++)
        #pragma unroll
        for (int r = 0; r < 8; r++) acc[q][r] = 0.f;
    const int mi = t & 15, ci = t >> 4;
    const int lm = t >> 2, ljj = (t & 3) * 4;
    const int wc = t & 127, wj = (t >> 7) * 8;
    for (int js = 0; js < 8; js++) {
        const int j0 = js * 16;
        {   int n = n0 + lm;
            float4 v = make_float4(0.f, 0.f, 0.f, 0.f);
            if (n < N) v = *(const float4*)(A + (size_t)n*CC + j0 + ljj);
            As[ljj+0][lm] = v.x; As[ljj+1][lm] = v.y;
            As[ljj+2][lm] = v.z; As[ljj+3][lm] = v.w;
        }
        {   float4 w0 = *(const float4*)(W + (size_t)wc*CC + j0 + wj);
            float4 w1 = *(const float4*)(W + (size_t)wc*CC + j0 + wj + 4);
            Ws[wj+0][wc] = w0.x; Ws[wj+1][wc] = w0.y; Ws[wj+2][wc] = w0.z; Ws[wj+3][wc] = w0.w;
            Ws[wj+4][wc] = w1.x; Ws[wj+5][wc] = w1.y; Ws[wj+6][wc] = w1.z; Ws[wj+7][wc] = w1.w;
        }
        __syncthreads();
        #pragma unroll
        for (int jp = 0; jp < 16; jp++) {
            float4 a  = *(const float4*)&As[jp][mi*4];
            float4 b0 = *(const float4*)&Ws[jp][ci*8];
            float4 b1 = *(const float4*)&Ws[jp][ci*8 + 4];
            float av[4] = {a.x, a.y, a.z, a.w};
            float wv[8] = {b0.x, b0.y, b0.z, b0.w, b1.x, b1.y, b1.z, b1.w};
            #pragma unroll
            for (int q = 0; q < 4; q++)
                #pragma unroll
                for (int r = 0; r < 8; r++) acc[q][r] += av[q] * wv[r];
        }
        __syncthreads();
    }
    const int c0 = ci * 8;
    #pragma unroll
    for (int q = 0; q < 4; q++) {
        int n = n0 + mi*4 + q;
        if (n < N) {
            float v[8];
            #pragma unroll
            for (int r = 0; r < 8; r++) {
                float bv = HASB ? bias[c0 + r] : 0.f;
                v[r] = (acc[q][r] + bv) * scale;
            }
            *(float4*)(out + (size_t)n*CC + c0)     = make_float4(v[0], v[1], v[2], v[3]);
            *(float4*)(out + (size_t)n*CC + c0 + 4) = make_float4(v[4], v[5], v[6], v[7]);
        }
    }
}

// ---------------- per-(point, head) attention ----------------
__global__ void __launch_bounds__(512) k_attn_r9(const int* __restrict__ coords, int N) {
    extern __shared__ float smem[];
    float* khs = smem;                 // [bk][d][h]
    float* vhs = smem + BB*KK*CC;
    const int t = threadIdx.x;
    for (int e = t; e < BB*KK*CC; e += 512) {
        int bk = e >> 7, r = e & 127, d = r >> 3, h = r & 7;
        int src = bk*CC + h*DHH + d;
        khs[e] = g_khv[src];
        vhs[e] = g_khv[BB*KK*CC + src];
    }
    __syncthreads();
    const int p = t >> 3, h = t & 7;
    const int n = blockIdx.x * 64 + p;
    if (n >= N) return;
    const int b = coords[4*n];
    float qr[16];
    #pragma unroll
    for (int u = 0; u < 4; u++)
        *(float4*)&qr[u*4] = *(const float4*)(g_q + (size_t)n*CC + h*DHH + u*4);
    float sc[KK];
    #pragma unroll
    for (int k = 0; k < KK; k++) {
        const float* kb = khs + ((b*KK + k)*DHH)*HH + h;
        float s = 0.f;
        #pragma unroll
        for (int d = 0; d < DHH; d++) s += qr[d] * kb[d*HH];
        sc[k] = s;
    }
    float m = sc[0];
    #pragma unroll
    for (int k = 1; k < KK; k++) m = fmaxf(m, sc[k]);
    float den = 0.f;
    #pragma unroll
    for (int k = 0; k < KK; k++) { sc[k] = __expf(sc[k] - m); den += sc[k]; }
    const float inv = 1.f / den;
    float od[16];
    #pragma unroll
    for (int d = 0; d < DHH; d++) od[d] = 0.f;
    #pragma unroll
    for (int k = 0; k < KK; k++) {
        float a = sc[k] * inv;
        const float* vb = vhs + ((b*KK + k)*DHH)*HH + h;
        #pragma unroll
        for (int d = 0; d < DHH; d++) od[d] += a * vb[d*HH];
    }
    #pragma unroll
    for (int u = 0; u < 4; u++)
        *(float4*)(g_o + (size_t)n*CC + h*DHH + u*4) = make_float4(od[u*4], od[u*4+1], od[u*4+2], od[u*4+3]);
}

// ---------------- launcher ----------------
extern "C" void kernel_launch(void* const* d_in, const int* in_sizes, int n_in,
                              void* d_out, int out_size) {
    const float* feats  = (const float*)d_in[0];
    const float* probs  = (const float*)d_in[1];
    const float* conv_w = (const float*)d_in[2];
    const float* gamma  = (const float*)d_in[3];
    const float* beta   = (const float*)d_in[4];
    const float* ipw    = (const float*)d_in[5];
    const float* ipb    = (const float*)d_in[6];
    const float* opw    = (const float*)d_in[7];
    const float* opb    = (const float*)d_in[8];
    const float* bw     = (const float*)d_in[9];
    const int*   coords = (const int*)d_in[10];
    float* y = (float*)d_out;
    int N = in_sizes[0] / CC;
    if (N > MAXN) N = MAXN;

    float *px, *pq, *po, *pao, *pws;
    cudaGetSymbolAddress((void**)&px,  g_x);
    cudaGetSymbolAddress((void**)&pq,  g_q);
    cudaGetSymbolAddress((void**)&po,  g_o);
    cudaGetSymbolAddress((void**)&pao, g_ao);
    cudaGetSymbolAddress((void**)&pws, g_wsum);

    cudaFuncSetAttribute(k_attn_r9, cudaFuncAttributeMaxDynamicSharedMemorySize, 2*BB*KK*CC*4);

    const int nt64 = (N + 63) / 64;
    k_init_r9<<<(BB*GG*GG*GG)/256, 256>>>(bw);
    k_scatter_r9<<<(N + 255)/256, 256>>>(coords, N);
    k_conv_r9<<<nt64, 256>>>(feats, conv_w, coords, N);
    k_bnstats_r9<<<(N + 255)/256, 128>>>(N);
    k_bnapply_r9<<<1024, 256>>>(gamma, beta, N);
    k_bk_r9<<<BB*KK, 256>>>(probs, coords, N);
    k_ctx_r9<<<dim3((N + 511)/512, BB), 256>>>(probs, coords, N);
    k_khv_r9<<<BB*KK, 256>>>(ipw, ipb);
    k_gemm_r9<true><<<nt64, 256>>>(px, ipw, ipb, pq, N, 0.25f);
    k_attn_r9<<<nt64, 512, 2*BB*KK*CC*4>>>(coords, N);
    k_gemm_r9<true><<<nt64, 256>>>(po, opw, opb, pao, N, 1.0f);
    k_gemm_r9<false><<<nt64, 256>>>(pao, pws, nullptr, y, N, 1.0f);
}

// round 10
// speedup vs baseline: 1.8185x; 1.8185x over previous
#include <cuda_runtime.h>
#include <cstdint>

#define CC   128
#define KK   32
#define HH   8
#define DHH  16
#define BB   4
#define GG   128
#define MAXN 100352

// ---------------- device scratch (R0-proven footprint ~239.3 MB) ----------------
__device__ int   g_grid[BB*GG*GG*GG];      // 32 MB voxel hash, cleared to -1 every call
__device__ float g_x  [MAXN*CC];           // conv accum -> BN/ReLU (zeroed every call)
__device__ float g_q  [MAXN*CC];           // ALIASED: int2 pair lists until q-projection
__device__ float g_o  [MAXN*CC];
__device__ float g_ao [MAXN*CC];
__device__ int   g_cnt[32];                // per-offset pair counts
__device__ float g_sum[CC];
__device__ float g_sumsq[CC];
__device__ float g_bkmax[BB*KK];
__device__ float g_bksum[BB*KK];
__device__ float g_ctx[BB*KK*CC];
__device__ float g_khv[2*BB*KK*CC];        // kh then vh, [bk][c]
__device__ float g_wsum[CC*CC];            // bottleneck_w[:, :C] + [:, C:]

// ---------------- init: grid=-1, x=0, counters, Wsum ----------------
__global__ void k_init_rA(const float* __restrict__ bw) {
    int i = blockIdx.x * blockDim.x + threadIdx.x;
    const int stride = gridDim.x * blockDim.x;
    const int tot = BB*GG*GG*GG;
    for (int idx = i; idx < tot; idx += stride) g_grid[idx] = -1;
    for (int idx = i; idx < MAXN*CC; idx += stride) g_x[idx] = 0.f;
    if (i < 32) g_cnt[i] = 0;
    if (i < BB*KK*CC) g_ctx[i] = 0.f;
    if (i < CC*CC) {
        int c = i >> 7, j = i & 127;
        g_wsum[i] = bw[c*2*CC + j] + bw[c*2*CC + CC + j];
    }
    if (i < CC) { g_sum[i] = 0.f; g_sumsq[i] = 0.f; }
}

__global__ void k_scatter_rA(const int* __restrict__ coords, int N) {
    int i = blockIdx.x * blockDim.x + threadIdx.x;
    if (i >= N) return;
    int b = coords[4*i], x = coords[4*i+1], y = coords[4*i+2], z = coords[4*i+3];
    g_grid[((b*GG + x)*GG + y)*GG + z] = i;
}

// ---------------- build per-offset (out,in) pair lists (warp-aggregated) ----------------
__global__ void k_pairs_rA(const int* __restrict__ coords, int N) {
    int2* pairs = (int2*)g_q;
    const int n = blockIdx.x * 256 + threadIdx.x;
    const int lane = threadIdx.x & 31;
    const bool valid = n < N;
    int b = 0, x = 0, y = 0, z = 0;
    if (valid) { b = coords[4*n]; x = coords[4*n+1]; y = coords[4*n+2]; z = coords[4*n+3]; }
    for (int k = 0; k < 27; k++) {
        int j = -1;
        if (valid) {
            int xx = x + k/9 - 1, yy = y + (k/3)%3 - 1, zz = z + k%3 - 1;
            if ((unsigned)xx < GG && (unsigned)yy < GG && (unsigned)zz < GG)
                j = g_grid[((b*GG + xx)*GG + yy)*GG + zz];
        }
        unsigned m = __ballot_sync(0xffffffffu, j >= 0);
        if (m) {
            int leader = __ffs(m) - 1;
            int base = 0;
            if (lane == leader) base = atomicAdd(&g_cnt[k], __popc(m));
            base = __shfl_sync(0xffffffffu, base, leader);
            if (j >= 0) {
                int pos = base + __popc(m & ((1u << lane) - 1));
                pairs[k*MAXN + pos] = make_int2(n, j);
            }
        }
    }
}

// ---------------- sparse conv: per-offset 64-pair x 128-out GEMM tiles ----------------
__global__ void __launch_bounds__(256) k_sconv_rA(const float* __restrict__ feats,
                                                  const float* __restrict__ cw, int N) {
    const int2* pairs = (const int2*)g_q;
    const int k   = blockIdx.y;
    const int cnt = g_cnt[k];
    const int p0  = blockIdx.x * 64;
    if (p0 >= cnt) return;
    __shared__ float As[16][64];
    __shared__ float Ws[16][CC];
    __shared__ int sn[64], sj[64];
    const int t = threadIdx.x;
    if (t < 64) {
        int idx = p0 + t;
        int2 pr = (idx < cnt) ? pairs[k*MAXN + idx] : make_int2(-1, -1);
        sn[t] = pr.x; sj[t] = pr.y;
    }
    __syncthreads();

    float acc[4][8];
    #pragma unroll
    for (int q = 0; q < 4; q++)
        #pragma unroll
        for (int r = 0; r < 8; r++) acc[q][r] = 0.f;

    const int mi = t & 15, ci = t >> 4;
    const int lm = t >> 2, ljj = (t & 3) * 4;
    const int wr = t >> 4, wcg = (t & 15) * 8;
    const float* Wk = cw + (size_t)k * CC * CC;   // [in][out]

    for (int js = 0; js < 8; js++) {
        const int j0 = js * 16;
        {   // A tile: As[j][p] = feats[sj[p]][j0+j]
            int j = sj[lm];
            float4 v = make_float4(0.f, 0.f, 0.f, 0.f);
            if (j >= 0) v = *(const float4*)(feats + (size_t)j*CC + j0 + ljj);
            As[ljj+0][lm] = v.x; As[ljj+1][lm] = v.y;
            As[ljj+2][lm] = v.z; As[ljj+3][lm] = v.w;
        }
        {   // W tile: Ws[j][c] = Wk[(j0+j)*CC + c]
            float4 w0 = *(const float4*)(Wk + (size_t)(j0 + wr)*CC + wcg);
            float4 w1 = *(const float4*)(Wk + (size_t)(j0 + wr)*CC + wcg + 4);
            *(float4*)&Ws[wr][wcg]     = w0;
            *(float4*)&Ws[wr][wcg + 4] = w1;
        }
        __syncthreads();
        #pragma unroll
        for (int jp = 0; jp < 16; jp++) {
            float4 a  = *(const float4*)&As[jp][mi*4];
            float4 b0 = *(const float4*)&Ws[jp][ci*8];
            float4 b1 = *(const float4*)&Ws[jp][ci*8 + 4];
            float av[4] = {a.x, a.y, a.z, a.w};
            float wv[8] = {b0.x, b0.y, b0.z, b0.w, b1.x, b1.y, b1.z, b1.w};
            #pragma unroll
            for (int q = 0; q < 4; q++)
                #pragma unroll
                for (int r = 0; r < 8; r++) acc[q][r] += av[q] * wv[r];
        }
        __syncthreads();
    }
    const int c0 = ci * 8;
    #pragma unroll
    for (int q = 0; q < 4; q++) {
        int pp = mi*4 + q;
        int n = sn[pp];
        if (n >= 0) {
            #pragma unroll
            for (int r = 0; r < 8; r++)
                atomicAdd(&g_x[(size_t)n*CC + c0 + r], acc[q][r]);
        }
    }
}

// ---------------- BN stats (coalesced) ----------------
__global__ void k_bnstats_rA(int N) {     // grid ceil(N/256), block 256
    const int c = threadIdx.x & 127, half = threadIdx.x >> 7;
    const int rend = min(blockIdx.x*256 + 256, N);
    float s = 0.f, s2 = 0.f;
    for (int r = blockIdx.x*256 + half; r < rend; r += 2) {
        float v = g_x[(size_t)r*CC + c];
        s += v; s2 += v * v;
    }
    atomicAdd(&g_sum[c], s);
    atomicAdd(&g_sumsq[c], s2);
}

__global__ void k_bnapply_rA(const float* __restrict__ gamma,
                             const float* __restrict__ beta, int N) {
    __shared__ float scl[CC], sft[CC];
    int t = threadIdx.x;
    if (t < CC) {
        float inv = 1.f / (float)N;
        float mu  = g_sum[t] * inv;
        float var = g_sumsq[t] * inv - mu * mu;
        float a   = gamma[t] * rsqrtf(var + 1e-5f);
        scl[t] = a; sft[t] = beta[t] - mu * a;
    }
    __syncthreads();
    const int tot = N * CC;
    for (int i = blockIdx.x * blockDim.x + t; i < tot; i += gridDim.x * blockDim.x) {
        float v = g_x[i] * scl[i & 127] + sft[i & 127];
        g_x[i] = v > 0.f ? v : 0.f;
    }
}

// ---------------- per-(b,k) softmax-over-n stats (R0) ----------------
__global__ void k_bk_rA(const float* __restrict__ probs, const int* __restrict__ coords, int N) {
    const int b = blockIdx.x >> 5, k = blockIdx.x & 31;
    __shared__ float red[256];
    const int t = threadIdx.x;
    float lm = -3.4e38f;
    for (int n = t; n < N; n += 256)
        if (coords[4*n] == b) lm = fmaxf(lm, probs[n*KK + k]);
    red[t] = lm; __syncthreads();
    for (int s = 128; s > 0; s >>= 1) { if (t < s) red[t] = fmaxf(red[t], red[t+s]); __syncthreads(); }
    float m = red[0]; __syncthreads();
    float ls = 0.f;
    for (int n = t; n < N; n += 256)
        if (coords[4*n] == b) ls += __expf(probs[n*KK + k] - m);
    red[t] = ls; __syncthreads();
    for (int s = 128; s > 0; s >>= 1) { if (t < s) red[t] += red[t+s]; __syncthreads(); }
    if (t == 0) { g_bkmax[blockIdx.x] = m; g_bksum[blockIdx.x] = red[0]; }
}

// ---------------- ctx[b,k,c] (R0) ----------------
__global__ void __launch_bounds__(256) k_ctx_rA(const float* __restrict__ probs,
                                                const int* __restrict__ coords, int N) {
    const int b = blockIdx.y;
    const int base0 = blockIdx.x * 512;
    __shared__ float sm[KK], sinv[KK];
    __shared__ float ws[8][KK];
    __shared__ float xs[8][CC];
    const int t = threadIdx.x;
    if (t < KK) { sm[t] = g_bkmax[b*KK + t]; sinv[t] = 1.f / g_bksum[b*KK + t]; }
    float acc[16];
    #pragma unroll
    for (int i = 0; i < 16; i++) acc[i] = 0.f;
    const int k = t >> 3, cg = t & 7;
    bool did = false;
    __syncthreads();
    for (int g = 0; g < 64; g++) {
        int nb = base0 + g * 8;
        if (nb >= N) break;
        int nchk = nb + (t & 7);
        int match = (nchk < N) && (coords[4*nchk] == b);
        if (!__syncthreads_or(match)) continue;
        did = true;
        {   int p = t >> 5, k2 = t & 31, nn = nb + p;
            int mt = (nn < N) && (coords[4*nn] == b);
            ws[p][k2] = mt ? __expf(probs[nn*KK + k2] - sm[k2]) * sinv[k2] : 0.f;
        }
        {   int p = t >> 5, c4 = (t & 31) * 4, nn = nb + p;
            float4 v = make_float4(0.f, 0.f, 0.f, 0.f);
            if (nn < N) v = *(const float4*)(g_x + (size_t)nn*CC + c4);
            *(float4*)&xs[p][c4] = v;
        }
        __syncthreads();
        #pragma unroll
        for (int p = 0; p < 8; p++) {
            float w = ws[p][k];
            #pragma unroll
            for (int i = 0; i < 16; i++) acc[i] += w * xs[p][cg + 8*i];
        }
        __syncthreads();
    }
    if (did) {
        #pragma unroll
        for (int i = 0; i < 16; i++)
            atomicAdd(&g_ctx[(b*KK + k)*CC + cg + 8*i], acc[i]);
    }
}

// ---------------- kh/vh (R0) ----------------
__global__ void k_khv_rA(const float* __restrict__ ipw, const float* __restrict__ ipb) {
    __shared__ float row[CC];
    const int bk = blockIdx.x, t = threadIdx.x;
    if (t < CC) row[t] = g_ctx[bk*CC + t];
    __syncthreads();
    const int c = t & 127, which = t >> 7;
    const float* wr = ipw + (size_t)(CC + which*CC + c) * CC;
    float s = ipb[CC + which*CC + c];
    #pragma unroll 8
    for (int j = 0; j < CC; j++) s += row[j] * wr[j];
    g_khv[which*BB*KK*CC + bk*CC + c] = s;
}

// ---------------- generic 64x128 SGEMM (R0) ----------------
template<bool HASB>
__global__ void __launch_bounds__(256) k_gemm_rA(const float* __restrict__ A,
                                                 const float* __restrict__ W,
                                                 const float* __restrict__ bias,
                                                 float* __restrict__ out,
                                                 int N, float scale) {
    __shared__ float As[16][64];
    __shared__ float Ws[16][CC];
    const int t  = threadIdx.x;
    const int n0 = blockIdx.x * 64;
    float acc[4][8];
    #pragma unroll
    for (int q = 0; q < 4; q++)
        #pragma unroll
        for (int r = 0; r < 8; r++) acc[q][r] = 0.f;
    const int mi = t & 15, ci = t >> 4;
    const int lm = t >> 2, ljj = (t & 3) * 4;
    const int wc = t & 127, wj = (t >> 7) * 8;
    for (int js = 0; js < 8; js++) {
        const int j0 = js * 16;
        {   int n = n0 + lm;
            float4 v = make_float4(0.f, 0.f, 0.f, 0.f);
            if (n < N) v = *(const float4*)(A + (size_t)n*CC + j0 + ljj);
            As[ljj+0][lm] = v.x; As[ljj+1][lm] = v.y;
            As[ljj+2][lm] = v.z; As[ljj+3][lm] = v.w;
        }
        {   float4 w0 = *(const float4*)(W + (size_t)wc*CC + j0 + wj);
            float4 w1 = *(const float4*)(W + (size_t)wc*CC + j0 + wj + 4);
            Ws[wj+0][wc] = w0.x; Ws[wj+1][wc] = w0.y; Ws[wj+2][wc] = w0.z; Ws[wj+3][wc] = w0.w;
            Ws[wj+4][wc] = w1.x; Ws[wj+5][wc] = w1.y; Ws[wj+6][wc] = w1.z; Ws[wj+7][wc] = w1.w;
        }
        __syncthreads();
        #pragma unroll
        for (int jp = 0; jp < 16; jp++) {
            float4 a  = *(const float4*)&As[jp][mi*4];
            float4 b0 = *(const float4*)&Ws[jp][ci*8];
            float4 b1 = *(const float4*)&Ws[jp][ci*8 + 4];
            float av[4] = {a.x, a.y, a.z, a.w};
            float wv[8] = {b0.x, b0.y, b0.z, b0.w, b1.x, b1.y, b1.z, b1.w};
            #pragma unroll
            for (int q = 0; q < 4; q++)
                #pragma unroll
                for (int r = 0; r < 8; r++) acc[q][r] += av[q] * wv[r];
        }
        __syncthreads();
    }
    const int c0 = ci * 8;
    #pragma unroll
    for (int q = 0; q < 4; q++) {
        int n = n0 + mi*4 + q;
        if (n < N) {
            float v[8];
            #pragma unroll
            for (int r = 0; r < 8; r++) {
                float bv = HASB ? bias[c0 + r] : 0.f;
                v[r] = (acc[q][r] + bv) * scale;
            }
            *(float4*)(out + (size_t)n*CC + c0)     = make_float4(v[0], v[1], v[2], v[3]);
            *(float4*)(out + (size_t)n*CC + c0 + 4) = make_float4(v[4], v[5], v[6], v[7]);
        }
    }
}

// ---------------- per-(point, head) attention (R0) ----------------
__global__ void __launch_bounds__(512) k_attn_rA(const int* __restrict__ coords, int N) {
    extern __shared__ float smem[];
    float* khs = smem;                 // [bk][d][h]
    float* vhs = smem + BB*KK*CC;
    const int t = threadIdx.x;
    for (int e = t; e < BB*KK*CC; e += 512) {
        int bk = e >> 7, r = e & 127, d = r >> 3, h = r & 7;
        int src = bk*CC + h*DHH + d;
        khs[e] = g_khv[src];
        vhs[e] = g_khv[BB*KK*CC + src];
    }
    __syncthreads();
    const int p = t >> 3, h = t & 7;
    const int n = blockIdx.x * 64 + p;
    if (n >= N) return;
    const int b = coords[4*n];
    float qr[16];
    #pragma unroll
    for (int u = 0; u < 4; u++)
        *(float4*)&qr[u*4] = *(const float4*)(g_q + (size_t)n*CC + h*DHH + u*4);
    float sc[KK];
    #pragma unroll
    for (int k = 0; k < KK; k++) {
        const float* kb = khs + ((b*KK + k)*DHH)*HH + h;
        float s = 0.f;
        #pragma unroll
        for (int d = 0; d < DHH; d++) s += qr[d] * kb[d*HH];
        sc[k] = s;
    }
    float m = sc[0];
    #pragma unroll
    for (int k = 1; k < KK; k++) m = fmaxf(m, sc[k]);
    float den = 0.f;
    #pragma unroll
    for (int k = 0; k < KK; k++) { sc[k] = __expf(sc[k] - m); den += sc[k]; }
    const float inv = 1.f / den;
    float od[16];
    #pragma unroll
    for (int d = 0; d < DHH; d++) od[d] = 0.f;
    #pragma unroll
    for (int k = 0; k < KK; k++) {
        float a = sc[k] * inv;
        const float* vb = vhs + ((b*KK + k)*DHH)*HH + h;
        #pragma unroll
        for (int d = 0; d < DHH; d++) od[d] += a * vb[d*HH];
    }
    #pragma unroll
    for (int u = 0; u < 4; u++)
        *(float4*)(g_o + (size_t)n*CC + h*DHH + u*4) = make_float4(od[u*4], od[u*4+1], od[u*4+2], od[u*4+3]);
}

// ---------------- launcher ----------------
extern "C" void kernel_launch(void* const* d_in, const int* in_sizes, int n_in,
                              void* d_out, int out_size) {
    const float* feats  = (const float*)d_in[0];
    const float* probs  = (const float*)d_in[1];
    const float* conv_w = (const float*)d_in[2];
    const float* gamma  = (const float*)d_in[3];
    const float* beta   = (const float*)d_in[4];
    const float* ipw    = (const float*)d_in[5];
    const float* ipb    = (const float*)d_in[6];
    const float* opw    = (const float*)d_in[7];
    const float* opb    = (const float*)d_in[8];
    const float* bw     = (const float*)d_in[9];
    const int*   coords = (const int*)d_in[10];
    float* y = (float*)d_out;
    int N = in_sizes[0] / CC;
    if (N > MAXN) N = MAXN;

    float *px, *pq, *po, *pao, *pws;
    cudaGetSymbolAddress((void**)&px,  g_x);
    cudaGetSymbolAddress((void**)&pq,  g_q);
    cudaGetSymbolAddress((void**)&po,  g_o);
    cudaGetSymbolAddress((void**)&pao, g_ao);
    cudaGetSymbolAddress((void**)&pws, g_wsum);

    cudaFuncSetAttribute(k_attn_rA, cudaFuncAttributeMaxDynamicSharedMemorySize, 2*BB*KK*CC*4);

    const int nt64 = (N + 63) / 64;
    k_init_rA<<<(BB*GG*GG*GG)/256, 256>>>(bw);
    k_scatter_rA<<<(N + 255)/256, 256>>>(coords, N);
    k_pairs_rA<<<(N + 255)/256, 256>>>(coords, N);
    k_sconv_rA<<<dim3(nt64, 27), 256>>>(feats, conv_w, N);
    k_bnstats_rA<<<(N + 255)/256, 256>>>(N);
    k_bnapply_rA<<<1024, 256>>>(gamma, beta, N);
    k_bk_rA<<<BB*KK, 256>>>(probs, coords, N);
    k_ctx_rA<<<dim3((N + 511)/512, BB), 256>>>(probs, coords, N);
    k_khv_rA<<<BB*KK, 256>>>(ipw, ipb);
    k_gemm_rA<true><<<nt64, 256>>>(px, ipw, ipb, pq, N, 0.25f);
    k_attn_rA<<<nt64, 512, 2*BB*KK*CC*4>>>(coords, N);
    k_gemm_rA<true><<<nt64, 256>>>(po, opw, opb, pao, N, 1.0f);
    k_gemm_rA<false><<<nt64, 256>>>(pao, pws, nullptr, y, N, 1.0f);
}

// round 11
// speedup vs baseline: 3.2555x; 1.7902x over previous
#include <cuda_runtime.h>
#include <cstdint>

#define CC   128
#define KK   32
#define HH   8
#define DHH  16
#define BB   4
#define GG   128
#define MAXN 100352

// ---------------- device scratch ----------------
__device__ int   g_grid[BB*GG*GG*GG];      // 0 = empty, else idx+1 (scatter rewrites same cells every call)
__device__ float g_x  [MAXN*CC];           // conv accum -> BN/ReLU (zeroed every call)
__device__ float g_q  [MAXN*CC];           // ALIASED: int2 pair lists until q-projection
__device__ float g_o  [MAXN*CC];
__device__ int   g_cnt[32];                // per-offset pair counts
__device__ int   g_boff[BB+1];             // batch row ranges
__device__ float g_sum[CC];
__device__ float g_sumsq[CC];
__device__ unsigned g_bkmaxu[BB*KK];       // order-preserving mapped max
__device__ float g_bkmax[BB*KK];
__device__ float g_bksum[BB*KK];
__device__ float g_ctx[BB*KK*CC];
__device__ float g_khv[2*BB*KK*CC];        // kh then vh, [bk][c]
__device__ float g_w2 [CC*CC];             // combined (wsum @ opw)
__device__ float g_b2 [CC];                // combined bias

// ---------------- helpers: order-preserving float<->uint ----------------
__device__ __forceinline__ unsigned fmap_rB(float f) {
    int i = __float_as_int(f);
    return (i >= 0) ? ((unsigned)i | 0x80000000u) : (unsigned)(~i);
}
__device__ __forceinline__ float funmap_rB(unsigned u) {
    int i = (u & 0x80000000u) ? (int)(u & 0x7fffffffu) : ~((int)u);
    return __int_as_float(i);
}

// ---------------- init: zero accumulators ----------------
__global__ void k_init_rB() {
    int i = blockIdx.x * blockDim.x + threadIdx.x;
    const int stride = gridDim.x * blockDim.x;
    for (int idx = i; idx < MAXN*32; idx += stride) ((float4*)g_x)[idx] = make_float4(0.f,0.f,0.f,0.f);
    if (i < 32) g_cnt[i] = 0;
    if (i < BB*KK*CC) g_ctx[i] = 0.f;
    if (i < BB*KK) { g_bkmaxu[i] = 0u; g_bksum[i] = 0.f; }
    if (i < CC) { g_sum[i] = 0.f; g_sumsq[i] = 0.f; }
}

__global__ void k_scatter_rB(const int* __restrict__ coords, int N) {
    int i = blockIdx.x * blockDim.x + threadIdx.x;
    if (i >= N) return;
    int b = coords[4*i], x = coords[4*i+1], y = coords[4*i+2], z = coords[4*i+3];
    g_grid[((b*GG + x)*GG + y)*GG + z] = i + 1;
}

// ---------------- batch range detection (coords batch-contiguous) ----------------
__global__ void k_bounds_rB(const int* __restrict__ coords, int N) {
    int n = blockIdx.x * blockDim.x + threadIdx.x;
    if (n >= N) return;
    if (n == 0) { g_boff[coords[0]] = 0; g_boff[BB] = N; }
    else if (coords[4*n] != coords[4*n - 4]) g_boff[coords[4*n]] = n;
}

// ---------------- build per-offset (out,in) pair lists ----------------
__global__ void k_pairs_rB(const int* __restrict__ coords, int N) {
    int2* pairs = (int2*)g_q;
    const int n = blockIdx.x * 256 + threadIdx.x;
    const int lane = threadIdx.x & 31;
    const bool valid = n < N;
    int b = 0, x = 0, y = 0, z = 0;
    if (valid) { b = coords[4*n]; x = coords[4*n+1]; y = coords[4*n+2]; z = coords[4*n+3]; }
    for (int k = 0; k < 27; k++) {
        int j = -1;
        if (valid) {
            int xx = x + k/9 - 1, yy = y + (k/3)%3 - 1, zz = z + k%3 - 1;
            if ((unsigned)xx < GG && (unsigned)yy < GG && (unsigned)zz < GG)
                j = g_grid[((b*GG + xx)*GG + yy)*GG + zz] - 1;
        }
        unsigned m = __ballot_sync(0xffffffffu, j >= 0);
        if (m) {
            int leader = __ffs(m) - 1;
            int base = 0;
            if (lane == leader) base = atomicAdd(&g_cnt[k], __popc(m));
            base = __shfl_sync(0xffffffffu, base, leader);
            if (j >= 0) {
                int pos = base + __popc(m & ((1u << lane) - 1));
                pairs[k*MAXN + pos] = make_int2(n, j);
            }
        }
    }
}

// ---------------- sparse conv (R10-proven) ----------------
__global__ void __launch_bounds__(256) k_sconv_rB(const float* __restrict__ feats,
                                                  const float* __restrict__ cw, int N) {
    const int2* pairs = (const int2*)g_q;
    const int k   = blockIdx.y;
    const int cnt = g_cnt[k];
    const int p0  = blockIdx.x * 64;
    if (p0 >= cnt) return;
    __shared__ float As[16][64];
    __shared__ float Ws[16][CC];
    __shared__ int sn[64], sj[64];
    const int t = threadIdx.x;
    if (t < 64) {
        int idx = p0 + t;
        int2 pr = (idx < cnt) ? pairs[k*MAXN + idx] : make_int2(-1, -1);
        sn[t] = pr.x; sj[t] = pr.y;
    }
    __syncthreads();

    float acc[4][8];
    #pragma unroll
    for (int q = 0; q < 4; q++)
        #pragma unroll
        for (int r = 0; r < 8; r++) acc[q][r] = 0.f;

    const int mi = t & 15, ci = t >> 4;
    const int lm = t >> 2, ljj = (t & 3) * 4;
    const int wr = t >> 4, wcg = (t & 15) * 8;
    const float* Wk = cw + (size_t)k * CC * CC;

    for (int js = 0; js < 8; js++) {
        const int j0 = js * 16;
        {   int j = sj[lm];
            float4 v = make_float4(0.f, 0.f, 0.f, 0.f);
            if (j >= 0) v = *(const float4*)(feats + (size_t)j*CC + j0 + ljj);
            As[ljj+0][lm] = v.x; As[ljj+1][lm] = v.y;
            As[ljj+2][lm] = v.z; As[ljj+3][lm] = v.w;
        }
        {   float4 w0 = *(const float4*)(Wk + (size_t)(j0 + wr)*CC + wcg);
            float4 w1 = *(const float4*)(Wk + (size_t)(j0 + wr)*CC + wcg + 4);
            *(float4*)&Ws[wr][wcg]     = w0;
            *(float4*)&Ws[wr][wcg + 4] = w1;
        }
        __syncthreads();
        #pragma unroll
        for (int jp = 0; jp < 16; jp++) {
            float4 a  = *(const float4*)&As[jp][mi*4];
            float4 b0 = *(const float4*)&Ws[jp][ci*8];
            float4 b1 = *(const float4*)&Ws[jp][ci*8 + 4];
            float av[4] = {a.x, a.y, a.z, a.w};
            float wv[8] = {b0.x, b0.y, b0.z, b0.w, b1.x, b1.y, b1.z, b1.w};
            #pragma unroll
            for (int q = 0; q < 4; q++)
                #pragma unroll
                for (int r = 0; r < 8; r++) acc[q][r] += av[q] * wv[r];
        }
        __syncthreads();
    }
    const int c0 = ci * 8;
    #pragma unroll
    for (int q = 0; q < 4; q++) {
        int n = sn[mi*4 + q];
        if (n >= 0) {
            #pragma unroll
            for (int r = 0; r < 8; r++)
                atomicAdd(&g_x[(size_t)n*CC + c0 + r], acc[q][r]);
        }
    }
}

// ---------------- BN stats (coalesced, R10-proven) ----------------
__global__ void k_bnstats_rB(int N) {
    const int c = threadIdx.x & 127, half = threadIdx.x >> 7;
    const int rend = min(blockIdx.x*256 + 256, N);
    float s = 0.f, s2 = 0.f;
    for (int r = blockIdx.x*256 + half; r < rend; r += 2) {
        float v = g_x[(size_t)r*CC + c];
        s += v; s2 += v * v;
    }
    atomicAdd(&g_sum[c], s);
    atomicAdd(&g_sumsq[c], s2);
}

__global__ void k_bnapply_rB(const float* __restrict__ gamma,
                             const float* __restrict__ beta, int N) {
    __shared__ float scl[CC], sft[CC];
    int t = threadIdx.x;
    if (t < CC) {
        float inv = 1.f / (float)N;
        float mu  = g_sum[t] * inv;
        float var = g_sumsq[t] * inv - mu * mu;
        float a   = gamma[t] * rsqrtf(var + 1e-5f);
        scl[t] = a; sft[t] = beta[t] - mu * a;
    }
    __syncthreads();
    const int tot = N * CC;
    for (int i = blockIdx.x * blockDim.x + t; i < tot; i += gridDim.x * blockDim.x) {
        float v = g_x[i] * scl[i & 127] + sft[i & 127];
        g_x[i] = v > 0.f ? v : 0.f;
    }
}

// ---------------- bk pass A: per-(b,k) max via mapped atomicMax ----------------
__global__ void k_bkmax_rB(const float* __restrict__ probs, const int* __restrict__ coords, int N) {
    __shared__ unsigned smax[BB*KK];
    const int t = threadIdx.x;
    if (t < BB*KK) smax[t] = 0u;
    __syncthreads();
    const int n = blockIdx.x * 256 + t;
    if (n < N) {
        const int b = coords[4*n];
        const float* pr = probs + (size_t)n * KK;
        #pragma unroll 8
        for (int k = 0; k < KK; k++)
            atomicMax(&smax[b*KK + k], fmap_rB(pr[k]));
    }
    __syncthreads();
    if (t < BB*KK && smax[t] != 0u) atomicMax(&g_bkmaxu[t], smax[t]);
}

// ---------------- bk pass B: per-(b,k) sum of exp ----------------
__global__ void k_bksum_rB(const float* __restrict__ probs, const int* __restrict__ coords, int N) {
    __shared__ float smx[BB*KK];
    __shared__ float ssum[BB*KK];
    const int t = threadIdx.x;
    if (t < BB*KK) {
        float f = funmap_rB(g_bkmaxu[t]);
        smx[t] = f;
        g_bkmax[t] = f;       // all blocks write identical values — benign
        ssum[t] = 0.f;
    }
    __syncthreads();
    const int n = blockIdx.x * 256 + t;
    if (n < N) {
        const int b = coords[4*n];
        const float* pr = probs + (size_t)n * KK;
        #pragma unroll 8
        for (int k = 0; k < KK; k++)
            atomicAdd(&ssum[b*KK + k], __expf(pr[k] - smx[b*KK + k]));
    }
    __syncthreads();
    if (t < BB*KK && ssum[t] != 0.f) atomicAdd(&g_bksum[t], ssum[t]);
}

// ---------------- ctx[b,k,c] over batch ranges ----------------
__global__ void __launch_bounds__(256) k_ctx_rB(const float* __restrict__ probs, int N) {
    const int b  = blockIdx.y;
    const int lo = g_boff[b], hi = g_boff[b+1];
    const int base = lo + blockIdx.x * 512;
    if (base >= hi) return;
    __shared__ float smx[KK], sinv[KK];
    __shared__ float ws[8][KK];
    __shared__ float xs[8][CC];
    const int t = threadIdx.x;
    if (t < KK) { smx[t] = g_bkmax[b*KK + t]; sinv[t] = 1.f / g_bksum[b*KK + t]; }
    float acc[16];
    #pragma unroll
    for (int i = 0; i < 16; i++) acc[i] = 0.f;
    const int k = t >> 3, cg = t & 7;
    __syncthreads();
    for (int g = 0; g < 64; g++) {
        int nb = base + g * 8;
        if (nb >= hi) break;
        {   int p = t >> 5, k2 = t & 31, nn = nb + p;
            ws[p][k2] = (nn < hi) ? __expf(probs[(size_t)nn*KK + k2] - smx[k2]) * sinv[k2] : 0.f;
        }
        {   int p = t >> 5, c4 = (t & 31) * 4, nn = nb + p;
            float4 v = make_float4(0.f, 0.f, 0.f, 0.f);
            if (nn < hi) v = *(const float4*)(g_x + (size_t)nn*CC + c4);
            *(float4*)&xs[p][c4] = v;
        }
        __syncthreads();
        #pragma unroll
        for (int p = 0; p < 8; p++) {
            float w = ws[p][k];
            #pragma unroll
            for (int i = 0; i < 16; i++) acc[i] += w * xs[p][cg + 8*i];
        }
        __syncthreads();
    }
    #pragma unroll
    for (int i = 0; i < 16; i++)
        atomicAdd(&g_ctx[(b*KK + k)*CC + cg + 8*i], acc[i]);
}

// ---------------- kh/vh (R0) ----------------
__global__ void k_khv_rB(const float* __restrict__ ipw, const float* __restrict__ ipb) {
    __shared__ float row[CC];
    const int bk = blockIdx.x, t = threadIdx.x;
    if (t < CC) row[t] = g_ctx[bk*CC + t];
    __syncthreads();
    const int c = t & 127, which = t >> 7;
    const float* wr = ipw + (size_t)(CC + which*CC + c) * CC;
    float s = ipb[CC + which*CC + c];
    #pragma unroll 8
    for (int j = 0; j < CC; j++) s += row[j] * wr[j];
    g_khv[which*BB*KK*CC + bk*CC + c] = s;
}

// ---------------- precompute combined W2 = wsum@opw, b2 = wsum@opb ----------------
__global__ void k_prew_rB(const float* __restrict__ bw, const float* __restrict__ opw,
                          const float* __restrict__ opb) {
    __shared__ float wrow[CC];
    const int c = blockIdx.x, j = threadIdx.x;
    wrow[j] = bw[c*2*CC + j] + bw[c*2*CC + CC + j];
    __syncthreads();
    float acc = 0.f;
    #pragma unroll 8
    for (int m = 0; m < CC; m++) acc += wrow[m] * opw[m*CC + j];
    g_w2[c*CC + j] = acc;
    if (j == 0) {
        float s = 0.f;
        for (int m = 0; m < CC; m++) s += wrow[m] * opb[m];
        g_b2[c] = s;
    }
}

// ---------------- generic 64x128 SGEMM (R0) ----------------
template<bool HASB>
__global__ void __launch_bounds__(256) k_gemm_rB(const float* __restrict__ A,
                                                 const float* __restrict__ W,
                                                 const float* __restrict__ bias,
                                                 float* __restrict__ out,
                                                 int N, float scale) {
    __shared__ float As[16][64];
    __shared__ float Ws[16][CC];
    const int t  = threadIdx.x;
    const int n0 = blockIdx.x * 64;
    float acc[4][8];
    #pragma unroll
    for (int q = 0; q < 4; q++)
        #pragma unroll
        for (int r = 0; r < 8; r++) acc[q][r] = 0.f;
    const int mi = t & 15, ci = t >> 4;
    const int lm = t >> 2, ljj = (t & 3) * 4;
    const int wc = t & 127, wj = (t >> 7) * 8;
    for (int js = 0; js < 8; js++) {
        const int j0 = js * 16;
        {   int n = n0 + lm;
            float4 v = make_float4(0.f, 0.f, 0.f, 0.f);
            if (n < N) v = *(const float4*)(A + (size_t)n*CC + j0 + ljj);
            As[ljj+0][lm] = v.x; As[ljj+1][lm] = v.y;
            As[ljj+2][lm] = v.z; As[ljj+3][lm] = v.w;
        }
        {   float4 w0 = *(const float4*)(W + (size_t)wc*CC + j0 + wj);
            float4 w1 = *(const float4*)(W + (size_t)wc*CC + j0 + wj + 4);
            Ws[wj+0][wc] = w0.x; Ws[wj+1][wc] = w0.y; Ws[wj+2][wc] = w0.z; Ws[wj+3][wc] = w0.w;
            Ws[wj+4][wc] = w1.x; Ws[wj+5][wc] = w1.y; Ws[wj+6][wc] = w1.z; Ws[wj+7][wc] = w1.w;
        }
        __syncthreads();
        #pragma unroll
        for (int jp = 0; jp < 16; jp++) {
            float4 a  = *(const float4*)&As[jp][mi*4];
            float4 b0 = *(const float4*)&Ws[jp][ci*8];
            float4 b1 = *(const float4*)&Ws[jp][ci*8 + 4];
            float av[4] = {a.x, a.y, a.z, a.w};
            float wv[8] = {b0.x, b0.y, b0.z, b0.w, b1.x, b1.y, b1.z, b1.w};
            #pragma unroll
            for (int q = 0; q < 4; q++)
                #pragma unroll
                for (int r = 0; r < 8; r++) acc[q][r] += av[q] * wv[r];
        }
        __syncthreads();
    }
    const int c0 = ci * 8;
    #pragma unroll
    for (int q = 0; q < 4; q++) {
        int n = n0 + mi*4 + q;
        if (n < N) {
            float v[8];
            #pragma unroll
            for (int r = 0; r < 8; r++) {
                float bv = HASB ? bias[c0 + r] : 0.f;
                v[r] = (acc[q][r] + bv) * scale;
            }
            *(float4*)(out + (size_t)n*CC + c0)     = make_float4(v[0], v[1], v[2], v[3]);
            *(float4*)(out + (size_t)n*CC + c0 + 4) = make_float4(v[4], v[5], v[6], v[7]);
        }
    }
}

// ---------------- per-(point, head) attention (R0) ----------------
__global__ void __launch_bounds__(512) k_attn_rB(const int* __restrict__ coords, int N) {
    extern __shared__ float smem[];
    float* khs = smem;                 // [bk][d][h]
    float* vhs = smem + BB*KK*CC;
    const int t = threadIdx.x;
    for (int e = t; e < BB*KK*CC; e += 512) {
        int bk = e >> 7, r = e & 127, d = r >> 3, h = r & 7;
        int src = bk*CC + h*DHH + d;
        khs[e] = g_khv[src];
        vhs[e] = g_khv[BB*KK*CC + src];
    }
    __syncthreads();
    const int p = t >> 3, h = t & 7;
    const int n = blockIdx.x * 64 + p;
    if (n >= N) return;
    const int b = coords[4*n];
    float qr[16];
    #pragma unroll
    for (int u = 0; u < 4; u++)
        *(float4*)&qr[u*4] = *(const float4*)(g_q + (size_t)n*CC + h*DHH + u*4);
    float sc[KK];
    #pragma unroll
    for (int k = 0; k < KK; k++) {
        const float* kb = khs + ((b*KK + k)*DHH)*HH + h;
        float s = 0.f;
        #pragma unroll
        for (int d = 0; d < DHH; d++) s += qr[d] * kb[d*HH];
        sc[k] = s;
    }
    float m = sc[0];
    #pragma unroll
    for (int k = 1; k < KK; k++) m = fmaxf(m, sc[k]);
    float den = 0.f;
    #pragma unroll
    for (int k = 0; k < KK; k++) { sc[k] = __expf(sc[k] - m); den += sc[k]; }
    const float inv = 1.f / den;
    float od[16];
    #pragma unroll
    for (int d = 0; d < DHH; d++) od[d] = 0.f;
    #pragma unroll
    for (int k = 0; k < KK; k++) {
        float a = sc[k] * inv;
        const float* vb = vhs + ((b*KK + k)*DHH)*HH + h;
        #pragma unroll
        for (int d = 0; d < DHH; d++) od[d] += a * vb[d*HH];
    }
    #pragma unroll
    for (int u = 0; u < 4; u++)
        *(float4*)(g_o + (size_t)n*CC + h*DHH + u*4) = make_float4(od[u*4], od[u*4+1], od[u*4+2], od[u*4+3]);
}

// ---------------- launcher ----------------
extern "C" void kernel_launch(void* const* d_in, const int* in_sizes, int n_in,
                              void* d_out, int out_size) {
    const float* feats  = (const float*)d_in[0];
    const float* probs  = (const float*)d_in[1];
    const float* conv_w = (const float*)d_in[2];
    const float* gamma  = (const float*)d_in[3];
    const float* beta   = (const float*)d_in[4];
    const float* ipw    = (const float*)d_in[5];
    const float* ipb    = (const float*)d_in[6];
    const float* opw    = (const float*)d_in[7];
    const float* opb    = (const float*)d_in[8];
    const float* bw     = (const float*)d_in[9];
    const int*   coords = (const int*)d_in[10];
    float* y = (float*)d_out;
    int N = in_sizes[0] / CC;
    if (N > MAXN) N = MAXN;

    float *px, *pq, *po, *pw2, *pb2;
    cudaGetSymbolAddress((void**)&px,  g_x);
    cudaGetSymbolAddress((void**)&pq,  g_q);
    cudaGetSymbolAddress((void**)&po,  g_o);
    cudaGetSymbolAddress((void**)&pw2, g_w2);
    cudaGetSymbolAddress((void**)&pb2, g_b2);

    cudaFuncSetAttribute(k_attn_rB, cudaFuncAttributeMaxDynamicSharedMemorySize, 2*BB*KK*CC*4);

    const int nt64  = (N + 63) / 64;
    const int nt256 = (N + 255) / 256;
    k_init_rB<<<512, 256>>>();
    k_scatter_rB<<<nt256, 256>>>(coords, N);
    k_bounds_rB<<<nt256, 256>>>(coords, N);
    k_pairs_rB<<<nt256, 256>>>(coords, N);
    k_sconv_rB<<<dim3(nt64, 27), 256>>>(feats, conv_w, N);
    k_bnstats_rB<<<nt256, 256>>>(N);
    k_bnapply_rB<<<1024, 256>>>(gamma, beta, N);
    k_bkmax_rB<<<nt256, 256>>>(probs, coords, N);
    k_bksum_rB<<<nt256, 256>>>(probs, coords, N);
    k_ctx_rB<<<dim3((N + 511)/512, BB), 256>>>(probs, N);
    k_khv_rB<<<BB*KK, 256>>>(ipw, ipb);
    k_prew_rB<<<CC, CC>>>(bw, opw, opb);
    k_gemm_rB<true><<<nt64, 256>>>(px, ipw, ipb, pq, N, 0.25f);
    k_attn_rB<<<nt64, 512, 2*BB*KK*CC*4>>>(coords, N);
    k_gemm_rB<true><<<nt64, 256>>>(po, pw2, pb2, y, N, 1.0f);
}